// round 11
// baseline (speedup 1.0000x reference)
#include <cuda_runtime.h>
#include <cstdint>

// HiddenMarkovModel: 100k 2-state chains x 500 steps, JAX threefry2x32
// (partitionable counter scheme), bit-exact.
// R11 = R10 resubmit (broker timeout, never ran): one warp per SMSP by
// construction (TPB=128, grid=131 <= 148 SMs => <=1 CTA/SM, wid%4 spreads 4
// warps over 4 SMSPs), 6 independent hash chains (3 particle-pairs) per
// thread => per-warp issue demand ~2.25 saturates a solo scheduler.
// Evidence: issue-eff tracks per-warp ILP (R7 2-chain 73.8%) not warp count
// (R9 1-chain 5.3 warps/SMSP 66.5%); R7 paid ~12% SMSP quantization.
// Keeps: IMAD-forced adds (fma pipe), prefetched keys, single-add s path,
// IMAD one-hot/threshold, pre-shifted int thresholds, STG.128 per pair.

#define MAX_FRAMES 512

// Per step: A = (k0, k1, ks2, ks2+1), B = (k0+2, k1+3, ks2+4, k0+5)
__device__ uint4    g_keysA[MAX_FRAMES];
__device__ uint4    g_keysB[MAX_FRAMES];
__device__ uint32_t g_thr[2];   // thresholds pre-shifted by 9: [state0, state1]
__device__ uint32_t g_one;      // runtime 1 (opaque to ptxas -> keeps IMAD)

__device__ __forceinline__ void tf2x32_full(uint32_t k0, uint32_t k1,
                                            uint32_t c0, uint32_t c1,
                                            uint32_t& o0, uint32_t& o1) {
    uint32_t ks2 = k0 ^ k1 ^ 0x1BD11BDAu;
    uint32_t x0 = c0 + k0;
    uint32_t x1 = c1 + k1;
#define TF_ROUND(R) { x0 += x1; x1 = __funnelshift_l(x1, x1, (R)); x1 ^= x0; }
    TF_ROUND(13) TF_ROUND(15) TF_ROUND(26) TF_ROUND(6)
    x0 += k1;  x1 += ks2 + 1u;
    TF_ROUND(17) TF_ROUND(29) TF_ROUND(16) TF_ROUND(24)
    x0 += ks2; x1 += k0 + 2u;
    TF_ROUND(13) TF_ROUND(15) TF_ROUND(26) TF_ROUND(6)
    x0 += k0;  x1 += k1 + 3u;
    TF_ROUND(17) TF_ROUND(29) TF_ROUND(16) TF_ROUND(24)
    x0 += k1;  x1 += ks2 + 4u;
    TF_ROUND(13) TF_ROUND(15) TF_ROUND(26) TF_ROUND(6)
    x0 += ks2; x1 += k0 + 5u;
#undef TF_ROUND
    o0 = x0; o1 = x1;
}

// ---------- setup kernel ----------
__global__ void hmm_setup_kernel(const int* __restrict__ seed_ptr, int frames) {
    const uint32_t seed = (uint32_t)seed_ptr[0];
    const uint32_t K0 = 0u, K1 = seed;       // root key (hi, lo)

    uint32_t kp0, kp1, ks0, ks1;
    tf2x32_full(K0, K1, 0u, 0u, kp0, kp1);   // kp
    tf2x32_full(K0, K1, 0u, 1u, ks0, ks1);   // ks

    const int j = threadIdx.x;
    if (j < frames) {
        uint32_t y0, y1;
        tf2x32_full(ks0, ks1, 0u, (uint32_t)j, y0, y1);   // keys[j]
        uint32_t ks2 = y0 ^ y1 ^ 0x1BD11BDAu;
        g_keysA[j] = make_uint4(y0, y1, ks2, ks2 + 1u);
        g_keysB[j] = make_uint4(y0 + 2u, y1 + 3u, ks2 + 4u, y0 + 5u);
    }

    if (j == 0) {
        uint32_t pa, pb;
        tf2x32_full(kp0, kp1, 0u, 0u, pa, pb);
        float u = __uint_as_float(((pa ^ pb) >> 9) | 0x3f800000u) - 1.0f;
        float p = u * 0.001f;
        // u < thr  <=>  (bits>>9) < ceil(thr*2^23)  <=>  bits < (ceil(..) << 9)
        g_thr[0] = ((uint32_t)ceilf(0.2f * 8388608.0f)) << 9;   // state 0
        g_thr[1] = ((uint32_t)ceilf(p    * 8388608.0f)) << 9;   // state 1
        g_one    = 1u;
    }
}

// ---------- main kernel: 6 chains (3 pairs) per thread ----------
#define TPB    128
#define NPAIRS 3
#define NCH    (2 * NPAIRS)

// add on the fma pipe: dst = a * one + b  (one == 1, opaque to ptxas)
#define FADD3(dst, a, b) \
    asm("mad.lo.u32 %0, %1, %2, %3;" : "=r"(dst) : "r"(a), "r"(one), "r"(b))
// dst = a * b + c  (all regs) on fma pipe
#define FMAD(dst, a, b, c) \
    asm("mad.lo.u32 %0, %1, %2, %3;" : "=r"(dst) : "r"(a), "r"(b), "r"(c))

__global__ __launch_bounds__(TPB)
void HiddenMarkovModel_kernel(const float* __restrict__ initial,
                              uint4* __restrict__ out,   // one uint4 = 2 particles
                              int N, int frames) {
    const int gid = blockIdx.x * TPB + threadIdx.x;
    const int TOT = gridDim.x * TPB;         // total threads (16768)
    const int P   = N >> 1;                  // particle pairs (50000)

    const uint32_t one = g_one;              // runtime 1
    const uint32_t T0  = g_thr[0];
    const uint32_t dT  = g_thr[1] - T0;      // thr = T0 + s*dT
    const uint32_t C   = 0x3F800000u;        // 1.0f bits
    const uint32_t nC  = 0u - C;             // -C (o = s*(-C)+C)

    // 3 pairs per thread, strided by TOT for coalescing
    int      q[NPAIRS];
    bool     v[NPAIRS];
    uint32_t s[NCH], base[NCH];
    uint4*   wp[NPAIRS];

#pragma unroll
    for (int j = 0; j < NPAIRS; ++j) {
        q[j] = gid + j * TOT;
        v[j] = (q[j] < P);
        float4 ini = make_float4(0.f, 0.f, 0.f, 0.f);
        if (v[j]) ini = *((const float4*)initial + q[j]);
        s[2*j]     = (ini.y > 0.5f) ? 1u : 0u;      // particle 2q
        s[2*j + 1] = (ini.w > 0.5f) ? 1u : 0u;      // particle 2q+1
        base[2*j]     = 4u * (uint32_t)q[j];        // counter base = 2*(2q)
        base[2*j + 1] = base[2*j] + 2u;
        wp[j] = out + q[j];
    }
    if (!v[0]) return;   // (never taken: grid sized so q[0] < P)

    // software pipeline: keys for iteration i live in qa/qb
    uint4 qa = __ldg(&g_keysA[0]);
    uint4 qb = __ldg(&g_keysB[0]);

#pragma unroll 1
    for (int i = 0; i < frames; ++i) {
        uint32_t x0[NCH], x1[NCH];
        // counter (0, base+s): x0 = k0; x1 = (base+k1) + s (one add on s path)
#pragma unroll
        for (int c = 0; c < NCH; ++c) {
            x0[c] = qa.x;
            uint32_t t;
            FADD3(t, base[c], qa.y);
            FADD3(x1[c], s[c], t);
        }

        // prefetch next iteration's keys into the shadow of the rounds
        const uint4 qa_n = __ldg(&g_keysA[i + 1]);
        const uint4 qb_n = __ldg(&g_keysB[i + 1]);

#define RALL(R) { _Pragma("unroll") \
    for (int c = 0; c < NCH; ++c) { \
        FADD3(x0[c], x1[c], x0[c]); \
        x1[c] = __funnelshift_l(x1[c], x1[c], (R)); \
        x1[c] ^= x0[c]; } }
#define INJALL(p0, p1) { _Pragma("unroll") \
    for (int c = 0; c < NCH; ++c) { \
        FADD3(x0[c], (p0), x0[c]); \
        FADD3(x1[c], (p1), x1[c]); } }

        RALL(13) RALL(15) RALL(26) RALL(6)
        INJALL(qa.y, qa.w)                     // += k1, ks2+1
        RALL(17) RALL(29) RALL(16) RALL(24)
        INJALL(qa.z, qb.x)                     // += ks2, k0+2
        RALL(13) RALL(15) RALL(26) RALL(6)
        INJALL(qa.x, qb.y)                     // += k0, k1+3
        RALL(17) RALL(29) RALL(16) RALL(24)
        INJALL(qa.y, qb.z)                     // += k1, ks2+4
        RALL(13) RALL(15) RALL(26) RALL(6)
        INJALL(qa.z, qb.w)                     // += ks2, k0+5
#undef RALL
#undef INJALL

        // state update per chain
#pragma unroll
        for (int c = 0; c < NCH; ++c) {
            const uint32_t bits = x0[c] ^ x1[c];
            uint32_t thr;
            FMAD(thr, s[c], dT, T0);           // thr = T0 + s*dT (fma pipe)
            s[c] ^= (bits < thr) ? 1u : 0u;
        }

        // output: one uint4 (2 one-hot float2s) per pair, STG.128 coalesced
#pragma unroll
        for (int j = 0; j < NPAIRS; ++j) {
            uint4 o;
            FMAD(o.x, s[2*j],     nC, C);
            FMAD(o.y, s[2*j],     C, 0u);
            FMAD(o.z, s[2*j + 1], nC, C);
            FMAD(o.w, s[2*j + 1], C, 0u);
            if (v[j]) *wp[j] = o;
            wp[j] += P;
        }

        qa = qa_n; qb = qb_n;                  // rotate pipeline
    }
}

extern "C" void kernel_launch(void* const* d_in, const int* in_sizes, int n_in,
                              void* d_out, int out_size) {
    const float* initial = (const float*)d_in[0];
    const int*   seed    = (const int*)d_in[1];
    const int N      = in_sizes[0] / 2;          // 100000
    const int frames = out_size / in_sizes[0];   // 500

    hmm_setup_kernel<<<1, MAX_FRAMES>>>(seed, frames);

    const int pairs   = N / 2;                           // 50000
    const int threads = (pairs + NPAIRS - 1) / NPAIRS;   // 16667
    const int grid    = (threads + TPB - 1) / TPB;       // 131 CTAs <= 148 SMs
    HiddenMarkovModel_kernel<<<grid, TPB>>>(initial, (uint4*)d_out, N, frames);
}

// round 14
// speedup vs baseline: 3.0883x; 3.0883x over previous
#include <cuda_runtime.h>
#include <cstdint>

// HiddenMarkovModel: 100k 2-state chains x 500 steps, JAX threefry2x32
// (partitionable counter scheme), bit-exact.
// R14 = R13 resubmit (broker timeout, never ran). Design:
//  - 3 chains/thread => 1042 warps => busiest SMSP carries 2 warps (R7's
//    incumbent carried 3 = ~12% quantization tax); per-warp ILP-3 sustains
//    issue-eff (R7 ILP-2 73.8% vs R9 ILP-1 66.5%).
//  - Keys in smem (LDS.128 broadcast), single store pointer, derived counter
//    bases: live set ~24-28 regs, under the 32-reg hard cap (R11: spill at
//    >32 demand => 3.6x regression).
//  - 3 wide-rotates/chain (IMAD.WIDE + fused LOP3, opaque multiplier) move
//    ~9 ops/iter from the binding alu pipe to fma (mechanism seen in R9 mix).

#define MAX_FRAMES 512

// Per step: A = (k0, k1, ks2, ks2+1), B = (k0+2, k1+3, ks2+4, k0+5)
__device__ uint4    g_keysA[MAX_FRAMES];
__device__ uint4    g_keysB[MAX_FRAMES];
__device__ uint32_t g_thr[2];   // thresholds pre-shifted by 9: [state0, state1]
__device__ uint32_t g_one;      // runtime 1     (opaque -> keeps IMAD)
__device__ uint32_t g_rot13;    // runtime 1<<13 (opaque -> keeps IMAD.WIDE)

__device__ __forceinline__ void tf2x32_full(uint32_t k0, uint32_t k1,
                                            uint32_t c0, uint32_t c1,
                                            uint32_t& o0, uint32_t& o1) {
    uint32_t ks2 = k0 ^ k1 ^ 0x1BD11BDAu;
    uint32_t x0 = c0 + k0;
    uint32_t x1 = c1 + k1;
#define TF_ROUND(R) { x0 += x1; x1 = __funnelshift_l(x1, x1, (R)); x1 ^= x0; }
    TF_ROUND(13) TF_ROUND(15) TF_ROUND(26) TF_ROUND(6)
    x0 += k1;  x1 += ks2 + 1u;
    TF_ROUND(17) TF_ROUND(29) TF_ROUND(16) TF_ROUND(24)
    x0 += ks2; x1 += k0 + 2u;
    TF_ROUND(13) TF_ROUND(15) TF_ROUND(26) TF_ROUND(6)
    x0 += k0;  x1 += k1 + 3u;
    TF_ROUND(17) TF_ROUND(29) TF_ROUND(16) TF_ROUND(24)
    x0 += k1;  x1 += ks2 + 4u;
    TF_ROUND(13) TF_ROUND(15) TF_ROUND(26) TF_ROUND(6)
    x0 += ks2; x1 += k0 + 5u;
#undef TF_ROUND
    o0 = x0; o1 = x1;
}

// ---------- setup kernel ----------
__global__ void hmm_setup_kernel(const int* __restrict__ seed_ptr, int frames) {
    const uint32_t seed = (uint32_t)seed_ptr[0];
    const uint32_t K0 = 0u, K1 = seed;       // root key (hi, lo)

    uint32_t kp0, kp1, ks0, ks1;
    tf2x32_full(K0, K1, 0u, 0u, kp0, kp1);   // kp
    tf2x32_full(K0, K1, 0u, 1u, ks0, ks1);   // ks

    const int j = threadIdx.x;
    if (j < frames) {
        uint32_t y0, y1;
        tf2x32_full(ks0, ks1, 0u, (uint32_t)j, y0, y1);   // keys[j]
        uint32_t ks2 = y0 ^ y1 ^ 0x1BD11BDAu;
        g_keysA[j] = make_uint4(y0, y1, ks2, ks2 + 1u);
        g_keysB[j] = make_uint4(y0 + 2u, y1 + 3u, ks2 + 4u, y0 + 5u);
    }

    if (j == 0) {
        uint32_t pa, pb;
        tf2x32_full(kp0, kp1, 0u, 0u, pa, pb);
        float u = __uint_as_float(((pa ^ pb) >> 9) | 0x3f800000u) - 1.0f;
        float p = u * 0.001f;
        // u < thr  <=>  (bits>>9) < ceil(thr*2^23)  <=>  bits < (ceil(..) << 9)
        g_thr[0] = ((uint32_t)ceilf(0.2f * 8388608.0f)) << 9;   // state 0
        g_thr[1] = ((uint32_t)ceilf(p    * 8388608.0f)) << 9;   // state 1
        g_one    = 1u;
        g_rot13  = 1u << 13;
    }
}

// ---------- main kernel: 3 chains per thread, keys in smem ----------
#define TPB 128
#define NCH 3

// add on the fma pipe: dst = a * one + b  (one == 1, opaque)
#define FADD3(dst, a, b) \
    asm("mad.lo.u32 %0, %1, %2, %3;" : "=r"(dst) : "r"(a), "r"(one), "r"(b))
// dst = a * b + c  (all regs) on fma pipe
#define FMAD(dst, a, b, c) \
    asm("mad.lo.u32 %0, %1, %2, %3;" : "=r"(dst) : "r"(a), "r"(b), "r"(c))

__global__ __launch_bounds__(TPB)
void HiddenMarkovModel_kernel(const float* __restrict__ initial,
                              uint2* __restrict__ out,
                              int N, int frames) {
    __shared__ uint4 skA[MAX_FRAMES];
    __shared__ uint4 skB[MAX_FRAMES];

    // cooperative key preload: frames x 32B
    for (int j = threadIdx.x; j < frames; j += TPB) {
        skA[j] = g_keysA[j];
        skB[j] = g_keysB[j];
    }
    __syncthreads();

    const int t   = blockIdx.x * TPB + threadIdx.x;   // = n0
    const int TOT = gridDim.x * TPB;                  // uniform (33408)

    const uint32_t one = g_one;              // runtime 1
    const uint32_t m13 = g_rot13;            // runtime 2^13
    const uint32_t T0  = g_thr[0];
    const uint32_t dT  = g_thr[1] - T0;      // thr = T0 + s*dT
    const uint32_t C   = 0x3F800000u;        // 1.0f bits
    const uint32_t nC  = 0u - C;             // -C (o.x = s*(-C)+C)
    const uint32_t D   = 2u * (uint32_t)TOT; // uniform chain-base stride

    // chains c handle particles n0 + c*TOT  (c=0,1 always valid; c=2 guarded)
    const bool v2 = (t + 2 * TOT) < N;
    uint32_t s[NCH];
    s[0] = (initial[2 * t + 1] > 0.5f) ? 1u : 0u;
    s[1] = (initial[2 * (t + TOT) + 1] > 0.5f) ? 1u : 0u;
    s[2] = v2 ? ((initial[2 * (t + 2 * TOT) + 1] > 0.5f) ? 1u : 0u) : 0u;
    const uint32_t base0 = 2u * (uint32_t)t;          // counter base, chain 0

    uint2* __restrict__ wp = out + t;        // single pointer; chains at
                                             // wp[0], wp[TOT], wp[2*TOT]

#pragma unroll 1
    for (int i = 0; i < frames; ++i) {
        const uint4 qa = skA[i];             // LDS.128 broadcast
        const uint4 qb = skB[i];

        uint32_t x0[NCH], x1[NCH];
        // counter (0, base_c + s): x0 = k0; x1 = (base_c + k1) + s
        // base_c = base0 + c*D; t0 computed once, uniform D added per chain
        {
            uint32_t t0;
            FADD3(t0, base0, qa.y);          // base0 + k1
#pragma unroll
            for (int c = 0; c < NCH; ++c) {
                x0[c] = qa.x;
                FADD3(x1[c], s[c], t0 + (uint32_t)c * D);  // uniform offset
            }
        }

// normal round: add(fma) + SHF(alu) + XOR(alu)
#define RALL(R) { _Pragma("unroll") \
    for (int c = 0; c < NCH; ++c) { \
        FADD3(x0[c], x1[c], x0[c]); \
        x1[c] = __funnelshift_l(x1[c], x1[c], (R)); \
        x1[c] ^= x0[c]; } }
// wide round (rot 13): add(fma) + IMAD.WIDE(fma) + LOP3 (lo|hi)^x0 (alu)
#define RALL_W13() { _Pragma("unroll") \
    for (int c = 0; c < NCH; ++c) { \
        FADD3(x0[c], x1[c], x0[c]); \
        unsigned long long _w; \
        asm("mul.wide.u32 %0, %1, %2;" : "=l"(_w) : "r"(x1[c]), "r"(m13)); \
        asm("lop3.b32 %0, %1, %2, %3, 0x56;" \
            : "=r"(x1[c]) : "r"((uint32_t)_w), "r"((uint32_t)(_w >> 32)), \
              "r"(x0[c])); } }
#define INJALL(p0, p1) { _Pragma("unroll") \
    for (int c = 0; c < NCH; ++c) { \
        FADD3(x0[c], (p0), x0[c]); \
        FADD3(x1[c], (p1), x1[c]); } }

        RALL_W13() RALL(15) RALL(26) RALL(6)
        INJALL(qa.y, qa.w)                   // += k1, ks2+1
        RALL(17) RALL(29) RALL(16) RALL(24)
        INJALL(qa.z, qb.x)                   // += ks2, k0+2
        RALL_W13() RALL(15) RALL(26) RALL(6)
        INJALL(qa.x, qb.y)                   // += k0, k1+3
        RALL(17) RALL(29) RALL(16) RALL(24)
        INJALL(qa.y, qb.z)                   // += k1, ks2+4
        RALL_W13() RALL(15) RALL(26) RALL(6)
        INJALL(qa.z, qb.w)                   // += ks2, k0+5
#undef RALL
#undef RALL_W13
#undef INJALL

        // state update + store per chain (stores at uniform offsets c*TOT)
#pragma unroll
        for (int c = 0; c < NCH; ++c) {
            const uint32_t bits = x0[c] ^ x1[c];
            uint32_t thr;
            FMAD(thr, s[c], dT, T0);         // thr = T0 + s*dT (fma pipe)
            s[c] ^= (bits < thr) ? 1u : 0u;

            uint2 o;                         // one-hot via IMAD (fma pipe)
            FMAD(o.x, s[c], nC, C);
            FMAD(o.y, s[c], C, 0u);
            if (c < 2 || v2) wp[c * TOT] = o;   // coalesced STG.64
        }
        wp += N;                             // advance one frame
    }
}

extern "C" void kernel_launch(void* const* d_in, const int* in_sizes, int n_in,
                              void* d_out, int out_size) {
    const float* initial = (const float*)d_in[0];
    const int*   seed    = (const int*)d_in[1];
    const int N      = in_sizes[0] / 2;          // 100000
    const int frames = out_size / in_sizes[0];   // 500

    hmm_setup_kernel<<<1, MAX_FRAMES>>>(seed, frames);

    const int threads = (N + NCH - 1) / NCH;         // 33334
    const int grid    = (threads + TPB - 1) / TPB;   // 261 CTAs -> 1042 warps
    HiddenMarkovModel_kernel<<<grid, TPB>>>(initial, (uint2*)d_out, N, frames);
}

// round 17
// speedup vs baseline: 3.0993x; 1.0036x over previous
#include <cuda_runtime.h>
#include <cstdint>

// HiddenMarkovModel: 100k 2-state chains x 500 steps, JAX threefry2x32
// (partitionable counter scheme), bit-exact.
// R17 = R15/R16 resubmit (two broker timeouts; design never ran). Clean
// 3-chain config: busiest-SMSP = 2 warps (vs R7's 3), per-warp ILP-3, keys
// via LDG register-prefetch, plain SHF rotates (wide-rotate retired: present
// in both ~207us regressions R9/R14), launch_bounds(TPB,1) so ptxas doesn't
// register-starve and serialize the chains (R11 pathology).

#define MAX_FRAMES 512

// Per step: A = (k0, k1, ks2, ks2+1), B = (k0+2, k1+3, ks2+4, k0+5)
__device__ uint4    g_keysA[MAX_FRAMES];
__device__ uint4    g_keysB[MAX_FRAMES];
__device__ uint32_t g_thr[2];   // thresholds pre-shifted by 9: [state0, state1]
__device__ uint32_t g_one;      // runtime 1 (opaque to ptxas -> keeps IMAD)

__device__ __forceinline__ void tf2x32_full(uint32_t k0, uint32_t k1,
                                            uint32_t c0, uint32_t c1,
                                            uint32_t& o0, uint32_t& o1) {
    uint32_t ks2 = k0 ^ k1 ^ 0x1BD11BDAu;
    uint32_t x0 = c0 + k0;
    uint32_t x1 = c1 + k1;
#define TF_ROUND(R) { x0 += x1; x1 = __funnelshift_l(x1, x1, (R)); x1 ^= x0; }
    TF_ROUND(13) TF_ROUND(15) TF_ROUND(26) TF_ROUND(6)
    x0 += k1;  x1 += ks2 + 1u;
    TF_ROUND(17) TF_ROUND(29) TF_ROUND(16) TF_ROUND(24)
    x0 += ks2; x1 += k0 + 2u;
    TF_ROUND(13) TF_ROUND(15) TF_ROUND(26) TF_ROUND(6)
    x0 += k0;  x1 += k1 + 3u;
    TF_ROUND(17) TF_ROUND(29) TF_ROUND(16) TF_ROUND(24)
    x0 += k1;  x1 += ks2 + 4u;
    TF_ROUND(13) TF_ROUND(15) TF_ROUND(26) TF_ROUND(6)
    x0 += ks2; x1 += k0 + 5u;
#undef TF_ROUND
    o0 = x0; o1 = x1;
}

// ---------- setup kernel ----------
__global__ void hmm_setup_kernel(const int* __restrict__ seed_ptr, int frames) {
    const uint32_t seed = (uint32_t)seed_ptr[0];
    const uint32_t K0 = 0u, K1 = seed;       // root key (hi, lo)

    uint32_t kp0, kp1, ks0, ks1;
    tf2x32_full(K0, K1, 0u, 0u, kp0, kp1);   // kp
    tf2x32_full(K0, K1, 0u, 1u, ks0, ks1);   // ks

    const int j = threadIdx.x;
    if (j < frames) {
        uint32_t y0, y1;
        tf2x32_full(ks0, ks1, 0u, (uint32_t)j, y0, y1);   // keys[j]
        uint32_t ks2 = y0 ^ y1 ^ 0x1BD11BDAu;
        g_keysA[j] = make_uint4(y0, y1, ks2, ks2 + 1u);
        g_keysB[j] = make_uint4(y0 + 2u, y1 + 3u, ks2 + 4u, y0 + 5u);
    }

    if (j == 0) {
        uint32_t pa, pb;
        tf2x32_full(kp0, kp1, 0u, 0u, pa, pb);
        float u = __uint_as_float(((pa ^ pb) >> 9) | 0x3f800000u) - 1.0f;
        float p = u * 0.001f;
        // u < thr  <=>  (bits>>9) < ceil(thr*2^23)  <=>  bits < (ceil(..) << 9)
        g_thr[0] = ((uint32_t)ceilf(0.2f * 8388608.0f)) << 9;   // state 0
        g_thr[1] = ((uint32_t)ceilf(p    * 8388608.0f)) << 9;   // state 1
        g_one    = 1u;
    }
}

// ---------- main kernel: 3 chains per thread, prefetched keys ----------
#define TPB 128
#define NCH 3

// add on the fma pipe: dst = a * one + b  (one == 1, opaque)
#define FADD3(dst, a, b) \
    asm("mad.lo.u32 %0, %1, %2, %3;" : "=r"(dst) : "r"(a), "r"(one), "r"(b))
// dst = a * b + c  (all regs) on fma pipe
#define FMAD(dst, a, b, c) \
    asm("mad.lo.u32 %0, %1, %2, %3;" : "=r"(dst) : "r"(a), "r"(b), "r"(c))

__global__ __launch_bounds__(TPB, 1)
void HiddenMarkovModel_kernel(const float* __restrict__ initial,
                              uint2* __restrict__ out,
                              int N, int frames) {
    const int t   = blockIdx.x * TPB + threadIdx.x;   // = n0
    const int TOT = gridDim.x * TPB;                  // uniform (33408)

    const uint32_t one = g_one;              // runtime 1
    const uint32_t T0  = g_thr[0];
    const uint32_t dT  = g_thr[1] - T0;      // thr = T0 + s*dT
    const uint32_t C   = 0x3F800000u;        // 1.0f bits
    const uint32_t nC  = 0u - C;             // -C (o.x = s*(-C)+C)
    const uint32_t D   = 2u * (uint32_t)TOT; // uniform chain-base stride

    // chains c handle particles n0 + c*TOT  (c=0,1 always valid; c=2 guarded)
    const bool v2 = (t + 2 * TOT) < N;
    uint32_t s[NCH];
    s[0] = (initial[2 * t + 1] > 0.5f) ? 1u : 0u;
    s[1] = (initial[2 * (t + TOT) + 1] > 0.5f) ? 1u : 0u;
    s[2] = v2 ? ((initial[2 * (t + 2 * TOT) + 1] > 0.5f) ? 1u : 0u) : 0u;
    const uint32_t base0 = 2u * (uint32_t)t;          // counter base, chain 0

    uint2* __restrict__ wp = out + t;        // single pointer; chains at
                                             // wp[0], wp[TOT], wp[2*TOT]

    // software pipeline: keys for iteration i live in qa/qb
    uint4 qa = __ldg(&g_keysA[0]);
    uint4 qb = __ldg(&g_keysB[0]);

#pragma unroll 1
    for (int i = 0; i < frames; ++i) {
        // prefetch next iteration's keys (i+1 <= 500 < MAX_FRAMES)
        const uint4 qa_n = __ldg(&g_keysA[i + 1]);
        const uint4 qb_n = __ldg(&g_keysB[i + 1]);

        uint32_t x0[NCH], x1[NCH];
        // counter (0, base_c + s): x0 = k0; x1 = (base_c + k1) + s
        {
            uint32_t t0;
            FADD3(t0, base0, qa.y);          // base0 + k1
#pragma unroll
            for (int c = 0; c < NCH; ++c) {
                x0[c] = qa.x;
                FADD3(x1[c], s[c], t0 + (uint32_t)c * D);  // uniform offset
            }
        }

// round: add(fma) + SHF(alu) + XOR(alu), all chains interleaved
#define RALL(R) { _Pragma("unroll") \
    for (int c = 0; c < NCH; ++c) { \
        FADD3(x0[c], x1[c], x0[c]); \
        x1[c] = __funnelshift_l(x1[c], x1[c], (R)); \
        x1[c] ^= x0[c]; } }
#define INJALL(p0, p1) { _Pragma("unroll") \
    for (int c = 0; c < NCH; ++c) { \
        FADD3(x0[c], (p0), x0[c]); \
        FADD3(x1[c], (p1), x1[c]); } }

        RALL(13) RALL(15) RALL(26) RALL(6)
        INJALL(qa.y, qa.w)                   // += k1, ks2+1
        RALL(17) RALL(29) RALL(16) RALL(24)
        INJALL(qa.z, qb.x)                   // += ks2, k0+2
        RALL(13) RALL(15) RALL(26) RALL(6)
        INJALL(qa.x, qb.y)                   // += k0, k1+3
        RALL(17) RALL(29) RALL(16) RALL(24)
        INJALL(qa.y, qb.z)                   // += k1, ks2+4
        RALL(13) RALL(15) RALL(26) RALL(6)
        INJALL(qa.z, qb.w)                   // += ks2, k0+5
#undef RALL
#undef INJALL

        // state update + store per chain (stores at uniform offsets c*TOT)
#pragma unroll
        for (int c = 0; c < NCH; ++c) {
            const uint32_t bits = x0[c] ^ x1[c];
            uint32_t thr;
            FMAD(thr, s[c], dT, T0);         // thr = T0 + s*dT (fma pipe)
            s[c] ^= (bits < thr) ? 1u : 0u;

            uint2 o;                         // one-hot via IMAD (fma pipe)
            FMAD(o.x, s[c], nC, C);
            FMAD(o.y, s[c], C, 0u);
            if (c < 2 || v2) wp[c * TOT] = o;   // coalesced STG.64
        }
        wp += N;                             // advance one frame

        qa = qa_n; qb = qb_n;                // rotate pipeline
    }
}

extern "C" void kernel_launch(void* const* d_in, const int* in_sizes, int n_in,
                              void* d_out, int out_size) {
    const float* initial = (const float*)d_in[0];
    const int*   seed    = (const int*)d_in[1];
    const int N      = in_sizes[0] / 2;          // 100000
    const int frames = out_size / in_sizes[0];   // 500

    hmm_setup_kernel<<<1, MAX_FRAMES>>>(seed, frames);

    const int threads = (N + NCH - 1) / NCH;         // 33334
    const int grid    = (threads + TPB - 1) / TPB;   // 261 CTAs -> 1044 warps
    HiddenMarkovModel_kernel<<<grid, TPB>>>(initial, (uint2*)d_out, N, frames);
}